// round 16
// baseline (speedup 1.0000x reference)
#include <cuda_runtime.h>
#include <cuda_fp16.h>
#include <cstdint>

// ============================================================================
// ConvAConnect: per-sample perturbed 3x3 SAME conv, B=32 H=W=64 Cin=128 F=256
// R16: occupancy experiment — 256 threads, 8 warps of 32x64 (acc 64 regs,
// <=128 total) so 2 CTAs/SM gives 4 warps/SMSP. Body = proven R13 scheme:
// fp16 X halo resident in smem (ldmatrix), B fp16 fragment table in L2 with
// register prefetch distance 2. fp16 m16n8k16, f32 accumulate. Barrier-free.
// ============================================================================
static constexpr int BATCH = 32;
static constexpr int CIN   = 128;
static constexpr int FOUT  = 256;
static constexpr int NG16  = 72;    // K=1152 / 16
static constexpr int HROWS = 4 * 66;               // halo rows (yy*66+xx)
static constexpr uint32_t HALO_BYTES = 264 * 256;  // 67584
static constexpr uint32_t SMEM_MB    = HALO_BYTES; // 128 floats
static constexpr uint32_t SMEM_TOTAL = HALO_BYTES + 512;   // 68096

// fp16 per-sample weights in exact m16n8k16 B-fragment order (same as R5-R15):
// half index = ((b*72 + g)*4 + wnq)*1024 + q*256 + lane*8 + e*4 + r*2 + p
__device__ __align__(256) __half g_wfrag[(size_t)BATCH * NG16 * 4096];

__device__ __forceinline__ uint32_t smem_u32(const void* p) {
    uint32_t a;
    asm("{ .reg .u64 t; cvta.to.shared.u64 t, %1; cvt.u32.u64 %0, t; }" : "=r"(a) : "l"(p));
    return a;
}
// 3-bit row-rotation swizzle on the 16B-segment index (conflict-free for
// LDSM octets over consecutive rows and for halo-fill STS).
__device__ __forceinline__ uint32_t swz3(uint32_t r) {
    return ((r & 1u) << 2) | ((r >> 1) & 3u);
}

// ============================================================================
// Prep: g_wfrag = frag_order(f16(W * Werr[b])). One block per (b, pos).
// ============================================================================
__global__ void __launch_bounds__(256) prep_wfrag(const float* __restrict__ W,
                                                  const float* __restrict__ Werr) {
    __shared__ float4 st4[512];                    // 8KB = 4096 halves
    __half* st = (__half*)st4;
    int blk = blockIdx.x;
    int b = blk / 9, pos = blk % 9;
    int f = threadIdx.x;                           // 0..255
    const float* wb = W    + (size_t)pos * CIN * FOUT + f;
    const float* eb = Werr + (size_t)(b * 9 + pos) * CIN * FOUT + f;
    const int wn = f >> 6, q = (f >> 4) & 3, e = (f >> 3) & 1;
    const int lane_base = (f & 7) * 4;

    for (int slab = 0; slab < 8; slab++) {         // 16 channels each
        __syncthreads();
#pragma unroll
        for (int ci = 0; ci < 16; ci++) {
            int c = slab * 16 + ci;
            float v = wb[(size_t)c * FOUT] * eb[(size_t)c * FOUT];
            int lane = lane_base + ((ci & 7) >> 1);
            int r = ci >> 3, p = ci & 1;
            st[wn * 1024 + q * 256 + lane * 8 + e * 4 + r * 2 + p] = __float2half_rn(v);
        }
        __syncthreads();
        int g = pos * 8 + slab;
        float4* dst = (float4*)(g_wfrag + (size_t)(b * NG16 + g) * 4096);
        dst[f * 2]     = st4[f * 2];
        dst[f * 2 + 1] = st4[f * 2 + 1];
    }
}

// ============================================================================
// Main: 2048 CTAs = 32 b x 32 mb (128 px = 2 image rows) x 2 nb (128 f).
// 256 threads, 8 warps: wm = wid>>1 (0..3, 32-px M slice), wn = wid&1
// (64-f half). 2 CTAs/SM -> 4 warps/SMSP.
// ============================================================================
__global__ void __launch_bounds__(256, 2)
conv_main(const float* __restrict__ X, const float* __restrict__ bias,
          const float* __restrict__ Berr, float* __restrict__ out) {
    extern __shared__ char smem[];
    const uint32_t sA = smem_u32(smem);
    float* sMB = (float*)(smem + SMEM_MB);

    const int t = threadIdx.x, l = t & 31, wid = t >> 5;
    const int b  = blockIdx.x >> 6;
    const int mb = (blockIdx.x >> 1) & 31;
    const int nb = blockIdx.x & 1;
    const int wm = wid >> 1, wn = wid & 1;

    if (t < 128) sMB[t] = bias[nb * 128 + t] * Berr[b * FOUT + nb * 128 + t];

    // ---- one-time X halo fill: rows r = yy*66+xx, fp16, zero-padded ----
    // warp per row (8 warps stride); lane l covers channels l*4..l*4+3
    for (int r = wid; r < HROWS; r += 8) {
        int yy = r / 66, xx = r - yy * 66;
        int y = mb * 2 - 1 + yy, x = xx - 1;
        bool valid = ((unsigned)y < 64u) && ((unsigned)x < 64u);
        float4 v = make_float4(0.f, 0.f, 0.f, 0.f);
        if (valid)
            v = ((const float4*)(X + (((size_t)b * 64 + y) * 64 + x) * CIN))[l];
        uint32_t h0, h1;
        asm volatile("cvt.rn.f16x2.f32 %0, %1, %2;" : "=r"(h0) : "f"(v.y), "f"(v.x));
        asm volatile("cvt.rn.f16x2.f32 %0, %1, %2;" : "=r"(h1) : "f"(v.w), "f"(v.z));
        uint32_t seg = (uint32_t)(l >> 1);
        uint32_t d = sA + (uint32_t)r * 256u + ((seg ^ swz3((uint32_t)r)) * 16u) +
                     (uint32_t)((l & 1) * 8);
        asm volatile("st.shared.v2.b32 [%0], {%1,%2};" :: "r"(d), "r"(h0), "r"(h1)
                     : "memory");
    }

    // ---- consumer ldmatrix lane addressing ----
    const int lm = l >> 3, lri = l & 7;
    const uint32_t segHi = (uint32_t)(lm >> 1);       // 0: k0-7, 1: k8-15
    // m within CTA = (wm>>1)*64(image row) + (wm&1)*32 + mt*16 + octet
    const int yrow = wm >> 1;                          // image row within block
    const int xoff0 = (wm & 1) * 32 + lri + (lm & 1) * 8;  // + mt*16

    // ---- B fragment base pointer (uint4 units: 8 halves each) ----
    const int wnq = nb * 2 + wn;                      // global f quarter
    const uint4* bp = (const uint4*)g_wfrag +
                      (size_t)b * NG16 * 512 + wnq * 128 + l;

    float acc[2][8][4];
#pragma unroll
    for (int mt = 0; mt < 2; mt++)
#pragma unroll
        for (int nt = 0; nt < 8; nt++)
#pragma unroll
            for (int qq = 0; qq < 4; qq++) acc[mt][nt][qq] = 0.f;

    // B prologue: g=0 and g=1 in regs (prefetch distance 2)
    uint4 bf[2][4];
#pragma unroll
    for (int qq = 0; qq < 4; qq++) bf[0][qq] = bp[qq * 32];
#pragma unroll
    for (int qq = 0; qq < 4; qq++) bf[1][qq] = bp[512 + qq * 32];
    __syncthreads();

    // ---- barrier-free mainloop: 9 positions x 8 k16 ----
    for (int s = 0; s < 9; s++) {
        int kh = s / 3, kw = s - kh * 3;
        const int rowoff = (yrow + kh) * 66 + kw + xoff0;

#pragma unroll
        for (int kk = 0; kk < 8; kk++) {
            int g = s * 8 + kk;

            // A fragments via ldmatrix.x4 (one per mt) from the halo
            uint32_t a[2][4];
            const uint32_t seg = (uint32_t)(kk * 2) + segHi;
#pragma unroll
            for (int mt = 0; mt < 2; mt++) {
                uint32_t rr = (uint32_t)(rowoff + mt * 16);
                uint32_t addr = sA + rr * 256u + ((seg ^ swz3(rr)) * 16u);
                asm volatile("ldmatrix.sync.aligned.m8n8.x4.shared.b16 "
                             "{%0,%1,%2,%3}, [%4];"
                             : "=r"(a[mt][0]), "=r"(a[mt][1]),
                               "=r"(a[mt][2]), "=r"(a[mt][3])
                             : "r"(addr));
            }

            const uint4* cb = bf[kk & 1];
#pragma unroll
            for (int mt = 0; mt < 2; mt++)
#pragma unroll
                for (int nt = 0; nt < 8; nt++) {
                    const uint4 qv = cb[nt >> 1];
                    uint32_t b0, b1;
                    if (nt & 1) { b0 = qv.z; b1 = qv.w; }
                    else        { b0 = qv.x; b1 = qv.y; }
                    asm volatile(
                        "mma.sync.aligned.m16n8k16.row.col.f32.f16.f16.f32 "
                        "{%0,%1,%2,%3}, {%4,%5,%6,%7}, {%8,%9}, {%0,%1,%2,%3};"
                        : "+f"(acc[mt][nt][0]), "+f"(acc[mt][nt][1]),
                          "+f"(acc[mt][nt][2]), "+f"(acc[mt][nt][3])
                        : "r"(a[mt][0]), "r"(a[mt][1]), "r"(a[mt][2]), "r"(a[mt][3]),
                          "r"(b0), "r"(b1));
                }

            // refill consumed B buffer with g+2 (prefetch distance 2)
            {
                int gn = (g + 2 < NG16) ? g + 2 : g;
                uint4* nbuf = bf[kk & 1];
#pragma unroll
                for (int qq = 0; qq < 4; qq++)
                    nbuf[qq] = bp[(size_t)gn * 512 + qq * 32];
            }
        }
    }

    // ---- epilogue: bias + relu + float2 stores ----
#pragma unroll
    for (int mt = 0; mt < 2; mt++) {
        int pix = mb * 128 + yrow * 64 + (wm & 1) * 32 + mt * 16 + (l >> 2);
        float* o = out + ((size_t)b * 4096 + pix) * FOUT + nb * 128;
#pragma unroll
        for (int nt = 0; nt < 8; nt++) {
            int f0 = wn * 64 + nt * 8 + (l & 3) * 2;
            float m0v = sMB[f0], m1v = sMB[f0 + 1];
            float2 r0, r1;
            r0.x = fmaxf(acc[mt][nt][0] + m0v, 0.f);
            r0.y = fmaxf(acc[mt][nt][1] + m1v, 0.f);
            r1.x = fmaxf(acc[mt][nt][2] + m0v, 0.f);
            r1.y = fmaxf(acc[mt][nt][3] + m1v, 0.f);
            *(float2*)(o + f0) = r0;
            *(float2*)(o + (size_t)8 * FOUT + f0) = r1;
        }
    }
}

// ============================================================================
// kernel_launch — size-match (elements or bytes) + positional fallback.
// ============================================================================
extern "C" void kernel_launch(void* const* d_in, const int* in_sizes, int n_in,
                              void* d_out, int out_size) {
    const long long EX = 33554432LL, EW = 294912LL, EBI = 256LL,
                    EWE = 9437184LL, EBE = 8192LL;

    auto pick = [&](long long elems) -> const float* {
        for (int i = 0; i < n_in; i++) {
            long long s = (long long)in_sizes[i];
            if (s == elems || s == elems * 4) return (const float*)d_in[i];
        }
        return nullptr;
    };
    const float* X    = pick(EX);
    const float* W    = pick(EW);
    const float* bias = pick(EBI);
    const float* Werr = pick(EWE);
    const float* Berr = pick(EBE);

    if (!X || !W || !bias || !Werr || !Berr) {
        if (n_in >= 5) {
            X    = (const float*)d_in[0];
            W    = (const float*)d_in[1];
            bias = (const float*)d_in[2];
            Werr = (const float*)d_in[3];
            Berr = (const float*)d_in[4];
        } else {
            return;
        }
    }

    float* out = (float*)d_out;

    cudaFuncSetAttribute(conv_main, cudaFuncAttributeMaxDynamicSharedMemorySize,
                         (int)SMEM_TOTAL);

    prep_wfrag<<<BATCH * 9, 256>>>(W, Werr);
    conv_main<<<BATCH * 64, 256, SMEM_TOTAL>>>(X, bias, Berr, out);
}